// round 2
// baseline (speedup 1.0000x reference)
#include <cuda_runtime.h>
#include <math.h>

// Problem dims (fixed)
#define SEQ   512
#define BATCH 64
#define IND   512
#define HID   1024
#define OUTD  512
#define CDIM  1536          // IND + HID
#define G4    4096          // 4*HID
#define NSPLIT 8            // K-splits in recurrence (K=1024 -> 128 each)
#define NTILES 32           // N-tiles in recurrence (4096/128)

// ---------------- scratch (static __device__ — no allocs allowed) ----------------
__device__ float g_Gx  [(size_t)SEQ * BATCH * G4];          // x-part of gates + bias
__device__ float g_Hall[(size_t)(SEQ + 1) * BATCH * HID];   // h_0..h_S
__device__ float g_c   [BATCH * HID];                       // cell state
__device__ float g_part[(size_t)NSPLIT * BATCH * G4];       // K-split partials (permuted cols)
__device__ int   g_cnt [NTILES];                            // per-ntile arrival tickets

// ---------------- f32x2 packed helpers (Blackwell, PTX-only) ----------------
typedef unsigned long long u64;
static __device__ __forceinline__ u64 pack2(float x, float y) {
    u64 r; asm("mov.b64 %0, {%1, %2};" : "=l"(r) : "f"(x), "f"(y)); return r;
}
static __device__ __forceinline__ void unpack2(u64 v, float &x, float &y) {
    asm("mov.b64 {%0, %1}, %2;" : "=f"(x), "=f"(y) : "l"(v));
}
static __device__ __forceinline__ u64 fma2(u64 a, u64 b, u64 c) {
    u64 d; asm("fma.rn.f32x2 %0, %1, %2, %3;" : "=l"(d) : "l"(a), "l"(b), "l"(c)); return d;
}
static __device__ __forceinline__ u64 add2(u64 a, u64 b) {
    u64 d; asm("add.rn.f32x2 %0, %1, %2;" : "=l"(d) : "l"(a), "l"(b)); return d;
}
static __device__ __forceinline__ float sigm(float x) { return 1.0f / (1.0f + __expf(-x)); }

// ---------------- init: zero h0, c, tickets ----------------
__global__ void k_init() {
    int idx = blockIdx.x * blockDim.x + threadIdx.x;
    int stride = gridDim.x * blockDim.x;
    for (int i = idx; i < BATCH * HID; i += stride) { g_Hall[i] = 0.0f; g_c[i] = 0.0f; }
    if (idx < NTILES) g_cnt[idx] = 0;
}

// =====================================================================
// kernel A: Gx = X @ Wx^T + b   (M=32768, N=4096, K=512)
// tile 128M x 128N, 256 threads, thread = 8m x 8n (4 f32x2 col-pairs)
// =====================================================================
__global__ __launch_bounds__(256, 2) void k_pregemm(
    const float* __restrict__ X,
    const float* __restrict__ Wf, const float* __restrict__ bf,
    const float* __restrict__ Wi, const float* __restrict__ bi,
    const float* __restrict__ Wo, const float* __restrict__ bo,
    const float* __restrict__ Wg, const float* __restrict__ bg)
{
    __shared__ u64   xs2[16][130];   // (x,x) broadcast pairs, [kk][m]
    __shared__ float ws [16][132];   // [kk][n-local]

    const int tid = threadIdx.x;
    const int m0 = blockIdx.y * 128;
    const int n0 = blockIdx.x * 128;          // 1024 % 128 == 0 -> single gate per tile
    const int q  = n0 >> 10;
    const float* Wq = (q == 0) ? Wf : (q == 1) ? Wi : (q == 2) ? Wo : Wg;
    const float* bq = (q == 0) ? bf : (q == 1) ? bi : (q == 2) ? bo : bg;
    const int j0 = n0 & 1023;

    // loaders: float4 along k
    const float* xp[2]; int xm[2], xk4[2];
    const float* wp[2]; int wc[2], wk4[2];
#pragma unroll
    for (int l = 0; l < 2; l++) {
        int e = tid + l * 256;
        int m = e >> 2, k4 = e & 3;
        xp[l] = X + (size_t)(m0 + m) * IND + k4 * 4; xm[l] = m; xk4[l] = k4;
        int c = e >> 2;
        wp[l] = Wq + (size_t)(j0 + c) * CDIM + k4 * 4; wc[l] = c; wk4[l] = k4;
    }

    u64 acc[8][4];
#pragma unroll
    for (int a = 0; a < 8; a++)
#pragma unroll
        for (int b = 0; b < 4; b++) acc[a][b] = 0ull;

    const int mrow = tid >> 4;       // 0..15 -> m = mrow*8..+7
    const int ncol = tid & 15;       // 0..15 -> n = ncol*8..+7

    float4 rx[2], rw[2];
#pragma unroll
    for (int l = 0; l < 2; l++) { rx[l] = *(const float4*)(xp[l]); rw[l] = *(const float4*)(wp[l]); }

    for (int kc = 0; kc < IND; kc += 16) {
#pragma unroll
        for (int l = 0; l < 2; l++) {
            xs2[xk4[l]*4+0][xm[l]] = pack2(rx[l].x, rx[l].x);
            xs2[xk4[l]*4+1][xm[l]] = pack2(rx[l].y, rx[l].y);
            xs2[xk4[l]*4+2][xm[l]] = pack2(rx[l].z, rx[l].z);
            xs2[xk4[l]*4+3][xm[l]] = pack2(rx[l].w, rx[l].w);
            ws[wk4[l]*4+0][wc[l]] = rw[l].x;
            ws[wk4[l]*4+1][wc[l]] = rw[l].y;
            ws[wk4[l]*4+2][wc[l]] = rw[l].z;
            ws[wk4[l]*4+3][wc[l]] = rw[l].w;
        }
        __syncthreads();
        if (kc + 16 < IND) {
#pragma unroll
            for (int l = 0; l < 2; l++) {
                rx[l] = *(const float4*)(xp[l] + kc + 16);
                rw[l] = *(const float4*)(wp[l] + kc + 16);
            }
        }
#pragma unroll
        for (int kk = 0; kk < 16; kk++) {
            ulonglong2 a01 = *reinterpret_cast<const ulonglong2*>(&xs2[kk][mrow*8 + 0]);
            ulonglong2 a23 = *reinterpret_cast<const ulonglong2*>(&xs2[kk][mrow*8 + 2]);
            ulonglong2 a45 = *reinterpret_cast<const ulonglong2*>(&xs2[kk][mrow*8 + 4]);
            ulonglong2 a67 = *reinterpret_cast<const ulonglong2*>(&xs2[kk][mrow*8 + 6]);
            ulonglong2 w01 = *reinterpret_cast<const ulonglong2*>(&ws[kk][ncol*8 + 0]);
            ulonglong2 w23 = *reinterpret_cast<const ulonglong2*>(&ws[kk][ncol*8 + 4]);
            acc[0][0]=fma2(a01.x,w01.x,acc[0][0]); acc[0][1]=fma2(a01.x,w01.y,acc[0][1]);
            acc[0][2]=fma2(a01.x,w23.x,acc[0][2]); acc[0][3]=fma2(a01.x,w23.y,acc[0][3]);
            acc[1][0]=fma2(a01.y,w01.x,acc[1][0]); acc[1][1]=fma2(a01.y,w01.y,acc[1][1]);
            acc[1][2]=fma2(a01.y,w23.x,acc[1][2]); acc[1][3]=fma2(a01.y,w23.y,acc[1][3]);
            acc[2][0]=fma2(a23.x,w01.x,acc[2][0]); acc[2][1]=fma2(a23.x,w01.y,acc[2][1]);
            acc[2][2]=fma2(a23.x,w23.x,acc[2][2]); acc[2][3]=fma2(a23.x,w23.y,acc[2][3]);
            acc[3][0]=fma2(a23.y,w01.x,acc[3][0]); acc[3][1]=fma2(a23.y,w01.y,acc[3][1]);
            acc[3][2]=fma2(a23.y,w23.x,acc[3][2]); acc[3][3]=fma2(a23.y,w23.y,acc[3][3]);
            acc[4][0]=fma2(a45.x,w01.x,acc[4][0]); acc[4][1]=fma2(a45.x,w01.y,acc[4][1]);
            acc[4][2]=fma2(a45.x,w23.x,acc[4][2]); acc[4][3]=fma2(a45.x,w23.y,acc[4][3]);
            acc[5][0]=fma2(a45.y,w01.x,acc[5][0]); acc[5][1]=fma2(a45.y,w01.y,acc[5][1]);
            acc[5][2]=fma2(a45.y,w23.x,acc[5][2]); acc[5][3]=fma2(a45.y,w23.y,acc[5][3]);
            acc[6][0]=fma2(a67.x,w01.x,acc[6][0]); acc[6][1]=fma2(a67.x,w01.y,acc[6][1]);
            acc[6][2]=fma2(a67.x,w23.x,acc[6][2]); acc[6][3]=fma2(a67.x,w23.y,acc[6][3]);
            acc[7][0]=fma2(a67.y,w01.x,acc[7][0]); acc[7][1]=fma2(a67.y,w01.y,acc[7][1]);
            acc[7][2]=fma2(a67.y,w23.x,acc[7][2]); acc[7][3]=fma2(a67.y,w23.y,acc[7][3]);
        }
        __syncthreads();
    }

    // epilogue: +bias (pairwise), store as 8B
#pragma unroll
    for (int p = 0; p < 4; p++) {
        int c = ncol * 8 + p * 2;
        u64 bb = pack2(bq[j0 + c], bq[j0 + c + 1]);
#pragma unroll
        for (int m = 0; m < 8; m++) {
            size_t row = (size_t)(m0 + mrow * 8 + m);
            *reinterpret_cast<u64*>(&g_Gx[row * G4 + n0 + c]) = add2(acc[m][p], bb);
        }
    }
}

// =====================================================================
// kernel B: one recurrence step.  grid (32 ntiles, 8 ksplits), 256 thr.
// N-tile = gate-interleaved 128 cols (4 gates x 32 j), K-split = 128.
// Last-arriving block per ntile reduces partials + Gx and does the
// fused activation / cell / hidden update.
// =====================================================================
__global__ __launch_bounds__(256, 2) void k_step(
    int t,
    const float* __restrict__ Wf, const float* __restrict__ Wi,
    const float* __restrict__ Wo, const float* __restrict__ Wg)
{
    __shared__ u64   hs2[16][66];    // (h,h) pairs, [kk][b]
    __shared__ float ws [16][132];   // [kk][c-local]
    __shared__ int s_old;

    const int tid   = threadIdx.x;
    const int ntile = blockIdx.x;    // 0..31
    const int split = blockIdx.y;    // 0..7
    const int koff  = split * 128;
    const int j0    = ntile * 32;    // j range of this tile
    const float* Hprev = g_Hall + (size_t)t * (BATCH * HID);

    // loaders (float4 along k)
    {
        const int hb  = tid >> 2;            // 0..63
        const int hk4 = tid & 3;
        const float* hp = Hprev + (size_t)hb * HID + koff + hk4 * 4;

        const float* wp[2]; int wc[2], wk4[2];
#pragma unroll
        for (int l = 0; l < 2; l++) {
            int e = tid + l * 256;
            int c = e >> 2, k4 = e & 3;
            int q = c >> 5, jn = c & 31;
            const float* Wq = (q == 0) ? Wf : (q == 1) ? Wi : (q == 2) ? Wo : Wg;
            wp[l] = Wq + (size_t)(j0 + jn) * CDIM + IND + koff + k4 * 4;
            wc[l] = c; wk4[l] = k4;
        }

        u64 acc[4][4];
#pragma unroll
        for (int a = 0; a < 4; a++)
#pragma unroll
            for (int b = 0; b < 4; b++) acc[a][b] = 0ull;

        const int b0 = (tid >> 4) * 4;   // 4 batch rows
        const int c0 = (tid & 15) * 8;   // 8 cols (4 pairs)

        float4 rh = *(const float4*)(hp);
        float4 rw0 = *(const float4*)(wp[0]);
        float4 rw1 = *(const float4*)(wp[1]);

        for (int kc = 0; kc < 128; kc += 16) {
            hs2[hk4*4+0][hb] = pack2(rh.x, rh.x);
            hs2[hk4*4+1][hb] = pack2(rh.y, rh.y);
            hs2[hk4*4+2][hb] = pack2(rh.z, rh.z);
            hs2[hk4*4+3][hb] = pack2(rh.w, rh.w);
            ws[wk4[0]*4+0][wc[0]] = rw0.x; ws[wk4[0]*4+1][wc[0]] = rw0.y;
            ws[wk4[0]*4+2][wc[0]] = rw0.z; ws[wk4[0]*4+3][wc[0]] = rw0.w;
            ws[wk4[1]*4+0][wc[1]] = rw1.x; ws[wk4[1]*4+1][wc[1]] = rw1.y;
            ws[wk4[1]*4+2][wc[1]] = rw1.z; ws[wk4[1]*4+3][wc[1]] = rw1.w;
            __syncthreads();
            if (kc + 16 < 128) {
                rh  = *(const float4*)(hp + kc + 16);
                rw0 = *(const float4*)(wp[0] + kc + 16);
                rw1 = *(const float4*)(wp[1] + kc + 16);
            }
#pragma unroll
            for (int kk = 0; kk < 16; kk++) {
                ulonglong2 a01 = *reinterpret_cast<const ulonglong2*>(&hs2[kk][b0 + 0]);
                ulonglong2 a23 = *reinterpret_cast<const ulonglong2*>(&hs2[kk][b0 + 2]);
                ulonglong2 w01 = *reinterpret_cast<const ulonglong2*>(&ws[kk][c0 + 0]);
                ulonglong2 w23 = *reinterpret_cast<const ulonglong2*>(&ws[kk][c0 + 4]);
                acc[0][0]=fma2(a01.x,w01.x,acc[0][0]); acc[0][1]=fma2(a01.x,w01.y,acc[0][1]);
                acc[0][2]=fma2(a01.x,w23.x,acc[0][2]); acc[0][3]=fma2(a01.x,w23.y,acc[0][3]);
                acc[1][0]=fma2(a01.y,w01.x,acc[1][0]); acc[1][1]=fma2(a01.y,w01.y,acc[1][1]);
                acc[1][2]=fma2(a01.y,w23.x,acc[1][2]); acc[1][3]=fma2(a01.y,w23.y,acc[1][3]);
                acc[2][0]=fma2(a23.x,w01.x,acc[2][0]); acc[2][1]=fma2(a23.x,w01.y,acc[2][1]);
                acc[2][2]=fma2(a23.x,w23.x,acc[2][2]); acc[2][3]=fma2(a23.x,w23.y,acc[2][3]);
                acc[3][0]=fma2(a23.y,w01.x,acc[3][0]); acc[3][1]=fma2(a23.y,w01.y,acc[3][1]);
                acc[3][2]=fma2(a23.y,w23.x,acc[3][2]); acc[3][3]=fma2(a23.y,w23.y,acc[3][3]);
            }
            __syncthreads();
        }

        // write K-split partial (permuted-col layout: pc = ntile*128 + c)
        float* part = g_part + (size_t)split * (BATCH * G4);
#pragma unroll
        for (int r = 0; r < 4; r++) {
#pragma unroll
            for (int p = 0; p < 4; p++) {
                int c = c0 + p * 2;
                *reinterpret_cast<u64*>(&part[(size_t)(b0 + r) * G4 + ntile * 128 + c]) = acc[r][p];
            }
        }
    }

    __threadfence();
    __syncthreads();
    if (tid == 0) s_old = atomicAdd(&g_cnt[ntile], 1);
    __syncthreads();
    if (s_old != NSPLIT * t + (NSPLIT - 1)) return;  // not last arrival
    __threadfence();                                  // make other splits' writes visible

    // finalize: this block owns j0..j0+31, all 64 b
    float* Hn = g_Hall + (size_t)(t + 1) * (BATCH * HID);
#pragma unroll
    for (int l = 0; l < 8; l++) {
        int e = tid + l * 256;        // 0..2047
        int b = e >> 5, jn = e & 31;
        size_t gxbase = ((size_t)t * BATCH + b) * G4;
        float gg[4];
#pragma unroll
        for (int q = 0; q < 4; q++) {
            int pc = ntile * 128 + q * 32 + jn;
            float s = g_Gx[gxbase + q * 1024 + j0 + jn];
#pragma unroll
            for (int sp = 0; sp < NSPLIT; sp++)
                s += g_part[((size_t)sp * BATCH + b) * G4 + pc];
            gg[q] = s;
        }
        float f  = sigm(gg[0]);
        float ii = sigm(gg[1]);
        float oo = sigm(gg[2]);
        float gt = tanhf(gg[3]);
        int ci = b * HID + j0 + jn;
        float cn = f * g_c[ci] + ii * gt;
        g_c[ci] = cn;
        Hn[ci] = oo * tanhf(cn);
    }
}

// =====================================================================
// kernel C: out = Hall[1..] @ Wy^T + by   (M=32768, N=512, K=1024)
// same 128x128 structure as k_pregemm
// =====================================================================
__global__ __launch_bounds__(256, 2) void k_out(
    const float* __restrict__ Wy, const float* __restrict__ by,
    float* __restrict__ Yout)
{
    __shared__ u64   xs2[16][130];
    __shared__ float ws [16][132];

    const int tid = threadIdx.x;
    const int m0 = blockIdx.y * 128;
    const int n0 = blockIdx.x * 128;
    const float* Hsrc = g_Hall + (size_t)(BATCH * HID);

    const float* xp[2]; int xm[2], xk4[2];
    const float* wp[2]; int wc[2], wk4[2];
#pragma unroll
    for (int l = 0; l < 2; l++) {
        int e = tid + l * 256;
        int m = e >> 2, k4 = e & 3;
        xp[l] = Hsrc + (size_t)(m0 + m) * HID + k4 * 4; xm[l] = m; xk4[l] = k4;
        int c = e >> 2;
        wp[l] = Wy + (size_t)(n0 + c) * HID + k4 * 4; wc[l] = c; wk4[l] = k4;
    }

    u64 acc[8][4];
#pragma unroll
    for (int a = 0; a < 8; a++)
#pragma unroll
        for (int b = 0; b < 4; b++) acc[a][b] = 0ull;

    const int mrow = tid >> 4;
    const int ncol = tid & 15;

    float4 rx[2], rw[2];
#pragma unroll
    for (int l = 0; l < 2; l++) { rx[l] = *(const float4*)(xp[l]); rw[l] = *(const float4*)(wp[l]); }

    for (int kc = 0; kc < HID; kc += 16) {
#pragma unroll
        for (int l = 0; l < 2; l++) {
            xs2[xk4[l]*4+0][xm[l]] = pack2(rx[l].x, rx[l].x);
            xs2[xk4[l]*4+1][xm[l]] = pack2(rx[l].y, rx[l].y);
            xs2[xk4[l]*4+2][xm[l]] = pack2(rx[l].z, rx[l].z);
            xs2[xk4[l]*4+3][xm[l]] = pack2(rx[l].w, rx[l].w);
            ws[wk4[l]*4+0][wc[l]] = rw[l].x;
            ws[wk4[l]*4+1][wc[l]] = rw[l].y;
            ws[wk4[l]*4+2][wc[l]] = rw[l].z;
            ws[wk4[l]*4+3][wc[l]] = rw[l].w;
        }
        __syncthreads();
        if (kc + 16 < HID) {
#pragma unroll
            for (int l = 0; l < 2; l++) {
                rx[l] = *(const float4*)(xp[l] + kc + 16);
                rw[l] = *(const float4*)(wp[l] + kc + 16);
            }
        }
#pragma unroll
        for (int kk = 0; kk < 16; kk++) {
            ulonglong2 a01 = *reinterpret_cast<const ulonglong2*>(&xs2[kk][mrow*8 + 0]);
            ulonglong2 a23 = *reinterpret_cast<const ulonglong2*>(&xs2[kk][mrow*8 + 2]);
            ulonglong2 a45 = *reinterpret_cast<const ulonglong2*>(&xs2[kk][mrow*8 + 4]);
            ulonglong2 a67 = *reinterpret_cast<const ulonglong2*>(&xs2[kk][mrow*8 + 6]);
            ulonglong2 w01 = *reinterpret_cast<const ulonglong2*>(&ws[kk][ncol*8 + 0]);
            ulonglong2 w23 = *reinterpret_cast<const ulonglong2*>(&ws[kk][ncol*8 + 4]);
            acc[0][0]=fma2(a01.x,w01.x,acc[0][0]); acc[0][1]=fma2(a01.x,w01.y,acc[0][1]);
            acc[0][2]=fma2(a01.x,w23.x,acc[0][2]); acc[0][3]=fma2(a01.x,w23.y,acc[0][3]);
            acc[1][0]=fma2(a01.y,w01.x,acc[1][0]); acc[1][1]=fma2(a01.y,w01.y,acc[1][1]);
            acc[1][2]=fma2(a01.y,w23.x,acc[1][2]); acc[1][3]=fma2(a01.y,w23.y,acc[1][3]);
            acc[2][0]=fma2(a23.x,w01.x,acc[2][0]); acc[2][1]=fma2(a23.x,w01.y,acc[2][1]);
            acc[2][2]=fma2(a23.x,w23.x,acc[2][2]); acc[2][3]=fma2(a23.x,w23.y,acc[2][3]);
            acc[3][0]=fma2(a23.y,w01.x,acc[3][0]); acc[3][1]=fma2(a23.y,w01.y,acc[3][1]);
            acc[3][2]=fma2(a23.y,w23.x,acc[3][2]); acc[3][3]=fma2(a23.y,w23.y,acc[3][3]);
            acc[4][0]=fma2(a45.x,w01.x,acc[4][0]); acc[4][1]=fma2(a45.x,w01.y,acc[4][1]);
            acc[4][2]=fma2(a45.x,w23.x,acc[4][2]); acc[4][3]=fma2(a45.x,w23.y,acc[4][3]);
            acc[5][0]=fma2(a45.y,w01.x,acc[5][0]); acc[5][1]=fma2(a45.y,w01.y,acc[5][1]);
            acc[5][2]=fma2(a45.y,w23.x,acc[5][2]); acc[5][3]=fma2(a45.y,w23.y,acc[5][3]);
            acc[6][0]=fma2(a67.x,w01.x,acc[6][0]); acc[6][1]=fma2(a67.x,w01.y,acc[6][1]);
            acc[6][2]=fma2(a67.x,w23.x,acc[6][2]); acc[6][3]=fma2(a67.x,w23.y,acc[6][3]);
            acc[7][0]=fma2(a67.y,w01.x,acc[7][0]); acc[7][1]=fma2(a67.y,w01.y,acc[7][1]);
            acc[7][2]=fma2(a67.y,w23.x,acc[7][2]); acc[7][3]=fma2(a67.y,w23.y,acc[7][3]);
        }
        __syncthreads();
    }

#pragma unroll
    for (int p = 0; p < 4; p++) {
        int c = ncol * 8 + p * 2;
        u64 bb = pack2(by[n0 + c], by[n0 + c + 1]);
#pragma unroll
        for (int m = 0; m < 8; m++) {
            size_t row = (size_t)(m0 + mrow * 8 + m);
            *reinterpret_cast<u64*>(&Yout[row * OUTD + n0 + c]) = add2(acc[m][p], bb);
        }
    }
}

// ---------------- launch ----------------
extern "C" void kernel_launch(void* const* d_in, const int* in_sizes, int n_in,
                              void* d_out, int out_size) {
    const float* x  = (const float*)d_in[0];
    const float* Wf = (const float*)d_in[1];
    const float* bf = (const float*)d_in[2];
    const float* Wi = (const float*)d_in[3];
    const float* bi = (const float*)d_in[4];
    const float* Wo = (const float*)d_in[5];
    const float* bo = (const float*)d_in[6];
    const float* Wg = (const float*)d_in[7];
    const float* bg = (const float*)d_in[8];
    const float* Wy = (const float*)d_in[9];
    const float* by = (const float*)d_in[10];
    float* out = (float*)d_out;

    k_init<<<64, 256>>>();
    k_pregemm<<<dim3(32, 256), 256>>>(x, Wf, bf, Wi, bi, Wo, bo, Wg, bg);
    for (int t = 0; t < SEQ; t++)
        k_step<<<dim3(NTILES, NSPLIT), 256>>>(t, Wf, Wi, Wo, Wg);
    k_out<<<dim3(4, 256), 256>>>(Wy, by, out);
}

// round 3
// speedup vs baseline: 1.5139x; 1.5139x over previous
#include <cuda_runtime.h>
#include <math.h>

// Problem dims (fixed)
#define SEQ   512
#define BATCH 64
#define IND   512
#define HID   1024
#define OUTD  512
#define CDIM  1536          // IND + HID
#define G4    4096          // 4*HID
#define KSPL  4             // K-splits in recurrence (1024/4 = 256 each)
#define KPER  256
#define NTIL  32            // ntiles (each owns 32 j-cols x 4 gates = 128 gate-cols)

// W smem: [k2][c] u64 pairs, padded row stride 130 u64
#define WPAD  130
#define WSK_BYTES (128 * WPAD * 8)          // 133120
#define HSK_BYTES (8 * 66 * 8)              // 4224
#define SMEM_RECUR (WSK_BYTES + HSK_BYTES)  // 137344

// ---------------- scratch (static __device__ — no allocs allowed) ----------------
__device__ float g_Gx  [(size_t)SEQ * BATCH * G4];          // x-part of gates + bias
__device__ float g_Hall[(size_t)(SEQ + 1) * BATCH * HID];   // h_0..h_S (h_0 unused)
__device__ float g_c   [BATCH * HID];                       // cell state
__device__ float g_part2[(size_t)NTIL * KSPL * BATCH * 128];// split partials
__device__ int   g_scnt [NTIL];                             // split arrival counters
__device__ int   g_hflag[NTIL];                             // h published step count

// ---------------- f32x2 packed helpers (Blackwell, PTX-only) ----------------
typedef unsigned long long u64;
static __device__ __forceinline__ u64 pack2(float x, float y) {
    u64 r; asm("mov.b64 %0, {%1, %2};" : "=l"(r) : "f"(x), "f"(y)); return r;
}
static __device__ __forceinline__ void unpack2(u64 v, float &x, float &y) {
    asm("mov.b64 {%0, %1}, %2;" : "=f"(x), "=f"(y) : "l"(v));
}
static __device__ __forceinline__ u64 fma2(u64 a, u64 b, u64 c) {
    u64 d; asm("fma.rn.f32x2 %0, %1, %2, %3;" : "=l"(d) : "l"(a), "l"(b), "l"(c)); return d;
}
static __device__ __forceinline__ u64 add2(u64 a, u64 b) {
    u64 d; asm("add.rn.f32x2 %0, %1, %2;" : "=l"(d) : "l"(a), "l"(b)); return d;
}
static __device__ __forceinline__ float sigm(float x) { return 1.0f / (1.0f + __expf(-x)); }

// ---------------- init: zero c, counters ----------------
__global__ void k_init() {
    int idx = blockIdx.x * blockDim.x + threadIdx.x;
    int stride = gridDim.x * blockDim.x;
    for (int i = idx; i < BATCH * HID; i += stride) g_c[i] = 0.0f;
    if (idx < NTIL) { g_scnt[idx] = 0; g_hflag[idx] = 0; }
}

// =====================================================================
// kernel A: Gx = X @ Wx^T + b   (M=32768, N=4096, K=512)  [unchanged]
// =====================================================================
__global__ __launch_bounds__(256, 2) void k_pregemm(
    const float* __restrict__ X,
    const float* __restrict__ Wf, const float* __restrict__ bf,
    const float* __restrict__ Wi, const float* __restrict__ bi,
    const float* __restrict__ Wo, const float* __restrict__ bo,
    const float* __restrict__ Wg, const float* __restrict__ bg)
{
    __shared__ u64   xs2[16][130];
    __shared__ float ws [16][132];

    const int tid = threadIdx.x;
    const int m0 = blockIdx.y * 128;
    const int n0 = blockIdx.x * 128;
    const int q  = n0 >> 10;
    const float* Wq = (q == 0) ? Wf : (q == 1) ? Wi : (q == 2) ? Wo : Wg;
    const float* bq = (q == 0) ? bf : (q == 1) ? bi : (q == 2) ? bo : bg;
    const int j0 = n0 & 1023;

    const float* xp[2]; int xm[2], xk4[2];
    const float* wp[2]; int wc[2], wk4[2];
#pragma unroll
    for (int l = 0; l < 2; l++) {
        int e = tid + l * 256;
        int m = e >> 2, k4 = e & 3;
        xp[l] = X + (size_t)(m0 + m) * IND + k4 * 4; xm[l] = m; xk4[l] = k4;
        int c = e >> 2;
        wp[l] = Wq + (size_t)(j0 + c) * CDIM + k4 * 4; wc[l] = c; wk4[l] = k4;
    }

    u64 acc[8][4];
#pragma unroll
    for (int a = 0; a < 8; a++)
#pragma unroll
        for (int b = 0; b < 4; b++) acc[a][b] = 0ull;

    const int mrow = tid >> 4;
    const int ncol = tid & 15;

    float4 rx[2], rw[2];
#pragma unroll
    for (int l = 0; l < 2; l++) { rx[l] = *(const float4*)(xp[l]); rw[l] = *(const float4*)(wp[l]); }

    for (int kc = 0; kc < IND; kc += 16) {
#pragma unroll
        for (int l = 0; l < 2; l++) {
            xs2[xk4[l]*4+0][xm[l]] = pack2(rx[l].x, rx[l].x);
            xs2[xk4[l]*4+1][xm[l]] = pack2(rx[l].y, rx[l].y);
            xs2[xk4[l]*4+2][xm[l]] = pack2(rx[l].z, rx[l].z);
            xs2[xk4[l]*4+3][xm[l]] = pack2(rx[l].w, rx[l].w);
            ws[wk4[l]*4+0][wc[l]] = rw[l].x;
            ws[wk4[l]*4+1][wc[l]] = rw[l].y;
            ws[wk4[l]*4+2][wc[l]] = rw[l].z;
            ws[wk4[l]*4+3][wc[l]] = rw[l].w;
        }
        __syncthreads();
        if (kc + 16 < IND) {
#pragma unroll
            for (int l = 0; l < 2; l++) {
                rx[l] = *(const float4*)(xp[l] + kc + 16);
                rw[l] = *(const float4*)(wp[l] + kc + 16);
            }
        }
#pragma unroll
        for (int kk = 0; kk < 16; kk++) {
            ulonglong2 a01 = *reinterpret_cast<const ulonglong2*>(&xs2[kk][mrow*8 + 0]);
            ulonglong2 a23 = *reinterpret_cast<const ulonglong2*>(&xs2[kk][mrow*8 + 2]);
            ulonglong2 a45 = *reinterpret_cast<const ulonglong2*>(&xs2[kk][mrow*8 + 4]);
            ulonglong2 a67 = *reinterpret_cast<const ulonglong2*>(&xs2[kk][mrow*8 + 6]);
            ulonglong2 w01 = *reinterpret_cast<const ulonglong2*>(&ws[kk][ncol*8 + 0]);
            ulonglong2 w23 = *reinterpret_cast<const ulonglong2*>(&ws[kk][ncol*8 + 4]);
            acc[0][0]=fma2(a01.x,w01.x,acc[0][0]); acc[0][1]=fma2(a01.x,w01.y,acc[0][1]);
            acc[0][2]=fma2(a01.x,w23.x,acc[0][2]); acc[0][3]=fma2(a01.x,w23.y,acc[0][3]);
            acc[1][0]=fma2(a01.y,w01.x,acc[1][0]); acc[1][1]=fma2(a01.y,w01.y,acc[1][1]);
            acc[1][2]=fma2(a01.y,w23.x,acc[1][2]); acc[1][3]=fma2(a01.y,w23.y,acc[1][3]);
            acc[2][0]=fma2(a23.x,w01.x,acc[2][0]); acc[2][1]=fma2(a23.x,w01.y,acc[2][1]);
            acc[2][2]=fma2(a23.x,w23.x,acc[2][2]); acc[2][3]=fma2(a23.x,w23.y,acc[2][3]);
            acc[3][0]=fma2(a23.y,w01.x,acc[3][0]); acc[3][1]=fma2(a23.y,w01.y,acc[3][1]);
            acc[3][2]=fma2(a23.y,w23.x,acc[3][2]); acc[3][3]=fma2(a23.y,w23.y,acc[3][3]);
            acc[4][0]=fma2(a45.x,w01.x,acc[4][0]); acc[4][1]=fma2(a45.x,w01.y,acc[4][1]);
            acc[4][2]=fma2(a45.x,w23.x,acc[4][2]); acc[4][3]=fma2(a45.x,w23.y,acc[4][3]);
            acc[5][0]=fma2(a45.y,w01.x,acc[5][0]); acc[5][1]=fma2(a45.y,w01.y,acc[5][1]);
            acc[5][2]=fma2(a45.y,w23.x,acc[5][2]); acc[5][3]=fma2(a45.y,w23.y,acc[5][3]);
            acc[6][0]=fma2(a67.x,w01.x,acc[6][0]); acc[6][1]=fma2(a67.x,w01.y,acc[6][1]);
            acc[6][2]=fma2(a67.x,w23.x,acc[6][2]); acc[6][3]=fma2(a67.x,w23.y,acc[6][3]);
            acc[7][0]=fma2(a67.y,w01.x,acc[7][0]); acc[7][1]=fma2(a67.y,w01.y,acc[7][1]);
            acc[7][2]=fma2(a67.y,w23.x,acc[7][2]); acc[7][3]=fma2(a67.y,w23.y,acc[7][3]);
        }
        __syncthreads();
    }

#pragma unroll
    for (int p = 0; p < 4; p++) {
        int c = ncol * 8 + p * 2;
        u64 bb = pack2(bq[j0 + c], bq[j0 + c + 1]);
#pragma unroll
        for (int m = 0; m < 8; m++) {
            size_t row = (size_t)(m0 + mrow * 8 + m);
            *reinterpret_cast<u64*>(&g_Gx[row * G4 + n0 + c]) = add2(acc[m][p], bb);
        }
    }
}

// =====================================================================
// kernel B: PERSISTENT recurrence. grid(32 ntiles, 4 splits), 512 thr.
// Wh slice (128 gate-cols x 256 k) lives in SMEM for all 512 steps.
// K-paired FFMA2: acc u64 = (even-k partial, odd-k partial).
// =====================================================================
__global__ __launch_bounds__(512, 1) void k_recur(
    const float* __restrict__ Wf, const float* __restrict__ Wi,
    const float* __restrict__ Wo, const float* __restrict__ Wg)
{
    extern __shared__ char smem[];
    u64* wsk = (u64*)smem;                      // [k2 0..127][c 0..127], stride WPAD
    u64* hsk = (u64*)(smem + WSK_BYTES);        // [k2l 0..7][b 0..63], stride 66

    const int tid  = threadIdx.x;
    const int n    = blockIdx.x;     // ntile: owns j = n*32..+31 (x4 gates)
    const int s    = blockIdx.y;     // split: k in [s*256, s*256+256)
    const int koff = s * KPER;

    // ---- one-time: load W slice into smem (u64 k-pairs) ----
#pragma unroll 4
    for (int l = 0; l < 32; l++) {
        int e = tid + l * 512;               // 0..16383
        int c = e >> 7, k2 = e & 127;
        int q = c >> 5, jn = c & 31;
        const float* Wq = (q == 0) ? Wf : (q == 1) ? Wi : (q == 2) ? Wo : Wg;
        wsk[k2 * WPAD + c] =
            *(const u64*)(Wq + (size_t)(n * 32 + jn) * CDIM + IND + koff + k2 * 2);
    }
    __syncthreads();

    // thread tile: 4b x 4c
    const int w    = tid >> 5, lane = tid & 31;
    const int b0   = (((w & 1) * 8) + (lane >> 2)) * 4;   // 0..60
    const int c0   = (((w >> 1) * 4) + (lane & 3)) * 4;   // 0..124
    const int hb   = tid >> 3;        // loader: batch row 0..63
    const int hk2  = tid & 7;         // loader: k2 within chunk 0..7

    volatile int* vhflag = (volatile int*)g_hflag;
    volatile int* vscnt  = (volatile int*)g_scnt;

    for (int t = 0; t < SEQ; t++) {
        if (t > 0) {
            // wait for h producers of our k-slice (+ our own ntile: partial-consumed guard)
            if (tid < 8) {
                int ni = s * 8 + tid;
                while (vhflag[ni] < t) __nanosleep(40);
            } else if (tid == 8) {
                while (vhflag[n] < t) __nanosleep(40);
            }
            __threadfence();
            __syncthreads();

            const float* Ht = g_Hall + (size_t)t * (BATCH * HID);
            const u64* hrow = (const u64*)(Ht + hb * HID + koff + hk2 * 2);

            u64 acc[4][4];
#pragma unroll
            for (int r = 0; r < 4; r++)
#pragma unroll
                for (int c = 0; c < 4; c++) acc[r][c] = 0ull;

            u64 rh = hrow[0];
#pragma unroll 1
            for (int ch = 0; ch < 16; ch++) {
                hsk[hk2 * 66 + hb] = rh;
                __syncthreads();
                if (ch < 15) rh = hrow[(ch + 1) * 8];   // next chunk (16 floats = 8 u64)
                const u64* wbase = wsk + ch * 8 * WPAD;
#pragma unroll
                for (int kk2 = 0; kk2 < 8; kk2++) {
                    const u64* hp = hsk + kk2 * 66;
                    const u64* wp2 = wbase + kk2 * WPAD;
                    ulonglong2 hA = *(const ulonglong2*)(hp + b0);
                    ulonglong2 hB = *(const ulonglong2*)(hp + b0 + 2);
                    ulonglong2 wA = *(const ulonglong2*)(wp2 + c0);
                    ulonglong2 wB = *(const ulonglong2*)(wp2 + c0 + 2);
                    acc[0][0]=fma2(hA.x,wA.x,acc[0][0]); acc[0][1]=fma2(hA.x,wA.y,acc[0][1]);
                    acc[0][2]=fma2(hA.x,wB.x,acc[0][2]); acc[0][3]=fma2(hA.x,wB.y,acc[0][3]);
                    acc[1][0]=fma2(hA.y,wA.x,acc[1][0]); acc[1][1]=fma2(hA.y,wA.y,acc[1][1]);
                    acc[1][2]=fma2(hA.y,wB.x,acc[1][2]); acc[1][3]=fma2(hA.y,wB.y,acc[1][3]);
                    acc[2][0]=fma2(hB.x,wA.x,acc[2][0]); acc[2][1]=fma2(hB.x,wA.y,acc[2][1]);
                    acc[2][2]=fma2(hB.x,wB.x,acc[2][2]); acc[2][3]=fma2(hB.x,wB.y,acc[2][3]);
                    acc[3][0]=fma2(hB.y,wA.x,acc[3][0]); acc[3][1]=fma2(hB.y,wA.y,acc[3][1]);
                    acc[3][2]=fma2(hB.y,wB.x,acc[3][2]); acc[3][3]=fma2(hB.y,wB.y,acc[3][3]);
                }
                __syncthreads();
            }

            // fold (even,odd) halves and publish partial (L2-coherent)
            float* pbase = g_part2 + ((size_t)(n * KSPL + s) * BATCH) * 128;
#pragma unroll
            for (int r = 0; r < 4; r++) {
                float4 v; float lo, hi;
                unpack2(acc[r][0], lo, hi); v.x = lo + hi;
                unpack2(acc[r][1], lo, hi); v.y = lo + hi;
                unpack2(acc[r][2], lo, hi); v.z = lo + hi;
                unpack2(acc[r][3], lo, hi); v.w = lo + hi;
                __stcg((float4*)(pbase + (size_t)(b0 + r) * 128 + c0), v);
            }
        }

        // arrive
        __threadfence();
        __syncthreads();
        if (tid == 0) atomicAdd(&g_scnt[n], 1);

        // rotating finalizer
        if (s == (t & 3)) {
            if (tid == 0) {
                int target = 4 * (t + 1);
                while (vscnt[n] < target) __nanosleep(40);
            }
            __syncthreads();
            __threadfence();

            const float* Gxt = g_Gx + (size_t)t * BATCH * G4;
            float* Hn = g_Hall + (size_t)(t + 1) * (BATCH * HID);
#pragma unroll
            for (int l = 0; l < 4; l++) {
                int e = tid + l * 512;          // 0..2047
                int b = e >> 5, jn = e & 31;
                float gg[4];
#pragma unroll
                for (int q = 0; q < 4; q++) {
                    float ssum = Gxt[(size_t)b * G4 + q * 1024 + n * 32 + jn];
                    if (t > 0) {
#pragma unroll
                        for (int sp = 0; sp < KSPL; sp++)
                            ssum += __ldcg(g_part2 + ((size_t)(n * KSPL + sp) * BATCH + b) * 128
                                           + q * 32 + jn);
                    }
                    gg[q] = ssum;
                }
                float f  = sigm(gg[0]);
                float ii = sigm(gg[1]);
                float oo = sigm(gg[2]);
                float gt = tanhf(gg[3]);
                int ci = b * HID + n * 32 + jn;
                float cn = f * __ldcg(&g_c[ci]) + ii * gt;
                __stcg(&g_c[ci], cn);
                Hn[ci] = oo * tanhf(cn);
            }
            __threadfence();
            __syncthreads();
            if (tid == 0) ((volatile int*)g_hflag)[n] = t + 1;
        }
    }
}

// =====================================================================
// kernel C: out = Hall[1..] @ Wy^T + by   (M=32768, N=512, K=1024)  [unchanged]
// =====================================================================
__global__ __launch_bounds__(256, 2) void k_out(
    const float* __restrict__ Wy, const float* __restrict__ by,
    float* __restrict__ Yout)
{
    __shared__ u64   xs2[16][130];
    __shared__ float ws [16][132];

    const int tid = threadIdx.x;
    const int m0 = blockIdx.y * 128;
    const int n0 = blockIdx.x * 128;
    const float* Hsrc = g_Hall + (size_t)(BATCH * HID);

    const float* xp[2]; int xm[2], xk4[2];
    const float* wp[2]; int wc[2], wk4[2];
#pragma unroll
    for (int l = 0; l < 2; l++) {
        int e = tid + l * 256;
        int m = e >> 2, k4 = e & 3;
        xp[l] = Hsrc + (size_t)(m0 + m) * HID + k4 * 4; xm[l] = m; xk4[l] = k4;
        int c = e >> 2;
        wp[l] = Wy + (size_t)(n0 + c) * HID + k4 * 4; wc[l] = c; wk4[l] = k4;
    }

    u64 acc[8][4];
#pragma unroll
    for (int a = 0; a < 8; a++)
#pragma unroll
        for (int b = 0; b < 4; b++) acc[a][b] = 0ull;

    const int mrow = tid >> 4;
    const int ncol = tid & 15;

    float4 rx[2], rw[2];
#pragma unroll
    for (int l = 0; l < 2; l++) { rx[l] = *(const float4*)(xp[l]); rw[l] = *(const float4*)(wp[l]); }

    for (int kc = 0; kc < HID; kc += 16) {
#pragma unroll
        for (int l = 0; l < 2; l++) {
            xs2[xk4[l]*4+0][xm[l]] = pack2(rx[l].x, rx[l].x);
            xs2[xk4[l]*4+1][xm[l]] = pack2(rx[l].y, rx[l].y);
            xs2[xk4[l]*4+2][xm[l]] = pack2(rx[l].z, rx[l].z);
            xs2[xk4[l]*4+3][xm[l]] = pack2(rx[l].w, rx[l].w);
            ws[wk4[l]*4+0][wc[l]] = rw[l].x;
            ws[wk4[l]*4+1][wc[l]] = rw[l].y;
            ws[wk4[l]*4+2][wc[l]] = rw[l].z;
            ws[wk4[l]*4+3][wc[l]] = rw[l].w;
        }
        __syncthreads();
        if (kc + 16 < HID) {
#pragma unroll
            for (int l = 0; l < 2; l++) {
                rx[l] = *(const float4*)(xp[l] + kc + 16);
                rw[l] = *(const float4*)(wp[l] + kc + 16);
            }
        }
#pragma unroll
        for (int kk = 0; kk < 16; kk++) {
            ulonglong2 a01 = *reinterpret_cast<const ulonglong2*>(&xs2[kk][mrow*8 + 0]);
            ulonglong2 a23 = *reinterpret_cast<const ulonglong2*>(&xs2[kk][mrow*8 + 2]);
            ulonglong2 a45 = *reinterpret_cast<const ulonglong2*>(&xs2[kk][mrow*8 + 4]);
            ulonglong2 a67 = *reinterpret_cast<const ulonglong2*>(&xs2[kk][mrow*8 + 6]);
            ulonglong2 w01 = *reinterpret_cast<const ulonglong2*>(&ws[kk][ncol*8 + 0]);
            ulonglong2 w23 = *reinterpret_cast<const ulonglong2*>(&ws[kk][ncol*8 + 4]);
            acc[0][0]=fma2(a01.x,w01.x,acc[0][0]); acc[0][1]=fma2(a01.x,w01.y,acc[0][1]);
            acc[0][2]=fma2(a01.x,w23.x,acc[0][2]); acc[0][3]=fma2(a01.x,w23.y,acc[0][3]);
            acc[1][0]=fma2(a01.y,w01.x,acc[1][0]); acc[1][1]=fma2(a01.y,w01.y,acc[1][1]);
            acc[1][2]=fma2(a01.y,w23.x,acc[1][2]); acc[1][3]=fma2(a01.y,w23.y,acc[1][3]);
            acc[2][0]=fma2(a23.x,w01.x,acc[2][0]); acc[2][1]=fma2(a23.x,w01.y,acc[2][1]);
            acc[2][2]=fma2(a23.x,w23.x,acc[2][2]); acc[2][3]=fma2(a23.x,w23.y,acc[2][3]);
            acc[3][0]=fma2(a23.y,w01.x,acc[3][0]); acc[3][1]=fma2(a23.y,w01.y,acc[3][1]);
            acc[3][2]=fma2(a23.y,w23.x,acc[3][2]); acc[3][3]=fma2(a23.y,w23.y,acc[3][3]);
            acc[4][0]=fma2(a45.x,w01.x,acc[4][0]); acc[4][1]=fma2(a45.x,w01.y,acc[4][1]);
            acc[4][2]=fma2(a45.x,w23.x,acc[4][2]); acc[4][3]=fma2(a45.x,w23.y,acc[4][3]);
            acc[5][0]=fma2(a45.y,w01.x,acc[5][0]); acc[5][1]=fma2(a45.y,w01.y,acc[5][1]);
            acc[5][2]=fma2(a45.y,w23.x,acc[5][2]); acc[5][3]=fma2(a45.y,w23.y,acc[5][3]);
            acc[6][0]=fma2(a67.x,w01.x,acc[6][0]); acc[6][1]=fma2(a67.x,w01.y,acc[6][1]);
            acc[6][2]=fma2(a67.x,w23.x,acc[6][2]); acc[6][3]=fma2(a67.x,w23.y,acc[6][3]);
            acc[7][0]=fma2(a67.y,w01.x,acc[7][0]); acc[7][1]=fma2(a67.y,w01.y,acc[7][1]);
            acc[7][2]=fma2(a67.y,w23.x,acc[7][2]); acc[7][3]=fma2(a67.y,w23.y,acc[7][3]);
        }
        __syncthreads();
    }

#pragma unroll
    for (int p = 0; p < 4; p++) {
        int c = ncol * 8 + p * 2;
        u64 bb = pack2(by[n0 + c], by[n0 + c + 1]);
#pragma unroll
        for (int m = 0; m < 8; m++) {
            size_t row = (size_t)(m0 + mrow * 8 + m);
            *reinterpret_cast<u64*>(&Yout[row * OUTD + n0 + c]) = add2(acc[m][p], bb);
        }
    }
}

// ---------------- launch ----------------
extern "C" void kernel_launch(void* const* d_in, const int* in_sizes, int n_in,
                              void* d_out, int out_size) {
    const float* x  = (const float*)d_in[0];
    const float* Wf = (const float*)d_in[1];
    const float* bf = (const float*)d_in[2];
    const float* Wi = (const float*)d_in[3];
    const float* bi = (const float*)d_in[4];
    const float* Wo = (const float*)d_in[5];
    const float* bo = (const float*)d_in[6];
    const float* Wg = (const float*)d_in[7];
    const float* bg = (const float*)d_in[8];
    const float* Wy = (const float*)d_in[9];
    const float* by = (const float*)d_in[10];
    float* out = (float*)d_out;

    cudaFuncSetAttribute(k_recur, cudaFuncAttributeMaxDynamicSharedMemorySize, SMEM_RECUR);

    k_init<<<64, 256>>>();
    k_pregemm<<<dim3(32, 256), 256>>>(x, Wf, bf, Wi, bi, Wo, bo, Wg, bg);
    k_recur<<<dim3(NTIL, KSPL), 512, SMEM_RECUR>>>(Wf, Wi, Wo, Wg);
    k_out<<<dim3(4, 256), 256>>>(Wy, by, out);
}